// round 2
// baseline (speedup 1.0000x reference)
#include <cuda_runtime.h>
#include <cuda_bf16.h>

// CenterLoss: loss = LAMBDA_C * mean_b sum_d (features[b,d] - centers[labels[b],d])^2
// B=65536, D=256, C=100000. Pure HBM-bound gather + reduce (~128 MB read).

#define BATCH     65536
#define FEAT_DIM  256
#define LAMBDA_C  1.0f

#define ROWS_PER_BLOCK 8              // 8 warps/block, 1 warp per row
#define NBLOCKS (BATCH / ROWS_PER_BLOCK)   // 8192

__device__ float g_partials[NBLOCKS];

__global__ __launch_bounds__(256, 8)
void center_loss_partial(const float* __restrict__ features,
                         const int*   __restrict__ labels,
                         const float* __restrict__ centers) {
    const int warp = threadIdx.x >> 5;
    const int lane = threadIdx.x & 31;
    const int row  = blockIdx.x * ROWS_PER_BLOCK + warp;

    const float4* frow = reinterpret_cast<const float4*>(features + (size_t)row * FEAT_DIM);
    const int lab = __ldg(&labels[row]);
    const float4* crow = reinterpret_cast<const float4*>(centers + (size_t)lab * FEAT_DIM);

    // 64 float4 per row / 32 lanes = 2 per lane. Issue all 4 loads up front (MLP=4).
    float4 a0 = __ldcs(&frow[lane]);        // streaming: features never reused
    float4 a1 = __ldcs(&frow[lane + 32]);
    float4 b0 = __ldg(&crow[lane]);         // centers may hit L2 on label collisions
    float4 b1 = __ldg(&crow[lane + 32]);

    float acc;
    {
        float d;
        d = a0.x - b0.x; acc = d * d;
        d = a0.y - b0.y; acc = fmaf(d, d, acc);
        d = a0.z - b0.z; acc = fmaf(d, d, acc);
        d = a0.w - b0.w; acc = fmaf(d, d, acc);
        d = a1.x - b1.x; acc = fmaf(d, d, acc);
        d = a1.y - b1.y; acc = fmaf(d, d, acc);
        d = a1.z - b1.z; acc = fmaf(d, d, acc);
        d = a1.w - b1.w; acc = fmaf(d, d, acc);
    }

    // warp reduce
    #pragma unroll
    for (int off = 16; off > 0; off >>= 1)
        acc += __shfl_xor_sync(0xffffffffu, acc, off);

    __shared__ float s[ROWS_PER_BLOCK];
    if (lane == 0) s[warp] = acc;
    __syncthreads();

    if (threadIdx.x == 0) {
        float t = 0.0f;
        #pragma unroll
        for (int i = 0; i < ROWS_PER_BLOCK; i++) t += s[i];
        g_partials[blockIdx.x] = t;
    }
}

__global__ __launch_bounds__(256, 1)
void center_loss_final(float* __restrict__ out) {
    // 8192 partials, 256 threads -> 32 each, accumulate in double.
    double acc = 0.0;
    #pragma unroll
    for (int i = 0; i < NBLOCKS / 256; i++)
        acc += (double)g_partials[threadIdx.x + i * 256];

    // warp reduce (double)
    #pragma unroll
    for (int off = 16; off > 0; off >>= 1)
        acc += __shfl_xor_sync(0xffffffffu, acc, off);

    __shared__ double s[8];
    const int warp = threadIdx.x >> 5;
    const int lane = threadIdx.x & 31;
    if (lane == 0) s[warp] = acc;
    __syncthreads();

    if (threadIdx.x == 0) {
        double t = 0.0;
        #pragma unroll
        for (int i = 0; i < 8; i++) t += s[i];
        out[0] = (float)(LAMBDA_C * (t / (double)BATCH));
    }
}

extern "C" void kernel_launch(void* const* d_in, const int* in_sizes, int n_in,
                              void* d_out, int out_size) {
    const float* features = (const float*)d_in[0];
    const int*   labels   = (const int*)d_in[1];
    const float* centers  = (const float*)d_in[2];
    float* out = (float*)d_out;

    center_loss_partial<<<NBLOCKS, 256>>>(features, labels, centers);
    center_loss_final<<<1, 256>>>(out);
}

// round 3
// speedup vs baseline: 1.3788x; 1.3788x over previous
#include <cuda_runtime.h>
#include <cuda_bf16.h>

// CenterLoss: loss = LAMBDA_C * mean_b sum_d (features[b,d] - centers[labels[b],d])^2
// B=65536, D=256, C=100000. HBM-bound gather (~112-128 MB effective read).
//
// R2: deterministic fixed-point integer atomic accumulation kills the 9.25us
// single-block FP64 reduction kernel from R1. Final kernel is <<<1,1>>>:
// read, scale, write, reset (self-restoring state for graph replay).

#define BATCH     65536
#define FEAT_DIM  256
#define LAMBDA_C  1.0

#define WARPS_PER_BLOCK 8
#define ROWS_PER_WARP   8
#define ROWS_PER_BLOCK  (WARPS_PER_BLOCK * ROWS_PER_WARP)      // 64
#define NBLOCKS         (BATCH / ROWS_PER_BLOCK)               // 1024

// Fixed-point scale: block partial ~<= 6e3 -> scaled ~2.5e10 fits in ll;
// total ~3.3e7 * 2^22 ~= 1.4e14 << 2^63. Integer atomics are order-invariant
// => bitwise-deterministic result on every launch.
#define FP_SCALE 4194304.0f   /* 2^22 */

__device__ unsigned long long g_acc;   // static-zero-initialized; reset by final kernel

__global__ __launch_bounds__(256, 8)
void center_loss_partial(const float* __restrict__ features,
                         const int*   __restrict__ labels,
                         const float* __restrict__ centers) {
    const int warp = threadIdx.x >> 5;
    const int lane = threadIdx.x & 31;
    const int row0 = blockIdx.x * ROWS_PER_BLOCK + warp * ROWS_PER_WARP;

    float acc = 0.0f;

    #pragma unroll
    for (int r = 0; r < ROWS_PER_WARP; r++) {
        const int row = row0 + r;
        const float4* frow = reinterpret_cast<const float4*>(features + (size_t)row * FEAT_DIM);
        const int lab = __ldg(&labels[row]);
        const float4* crow = reinterpret_cast<const float4*>(centers + (size_t)lab * FEAT_DIM);

        // 64 float4 per row / 32 lanes = 2 per lane; all 4 loads issued up front.
        float4 a0 = __ldcs(&frow[lane]);        // features: streaming, never reused
        float4 a1 = __ldcs(&frow[lane + 32]);
        float4 b0 = __ldg(&crow[lane]);         // centers: L2 reuse on label collisions
        float4 b1 = __ldg(&crow[lane + 32]);

        float d;
        d = a0.x - b0.x; acc = fmaf(d, d, acc);
        d = a0.y - b0.y; acc = fmaf(d, d, acc);
        d = a0.z - b0.z; acc = fmaf(d, d, acc);
        d = a0.w - b0.w; acc = fmaf(d, d, acc);
        d = a1.x - b1.x; acc = fmaf(d, d, acc);
        d = a1.y - b1.y; acc = fmaf(d, d, acc);
        d = a1.z - b1.z; acc = fmaf(d, d, acc);
        d = a1.w - b1.w; acc = fmaf(d, d, acc);
    }

    // warp reduce (float)
    #pragma unroll
    for (int off = 16; off > 0; off >>= 1)
        acc += __shfl_xor_sync(0xffffffffu, acc, off);

    __shared__ float s[WARPS_PER_BLOCK];
    if (lane == 0) s[warp] = acc;
    __syncthreads();

    if (threadIdx.x == 0) {
        float t = 0.0f;
        #pragma unroll
        for (int i = 0; i < WARPS_PER_BLOCK; i++) t += s[i];
        // One integer RED per block (1024 total, single address, hidden under mem phase).
        atomicAdd(&g_acc, (unsigned long long)llrintf(t * FP_SCALE));
    }
}

__global__ void center_loss_final(float* __restrict__ out) {
    double t = (double)g_acc / (double)FP_SCALE;
    out[0] = (float)(LAMBDA_C * (t / (double)BATCH));
    g_acc = 0ull;   // self-restore for next graph replay
}

extern "C" void kernel_launch(void* const* d_in, const int* in_sizes, int n_in,
                              void* d_out, int out_size) {
    const float* features = (const float*)d_in[0];
    const int*   labels   = (const int*)d_in[1];
    const float* centers  = (const float*)d_in[2];
    float* out = (float*)d_out;

    center_loss_partial<<<NBLOCKS, 256>>>(features, labels, centers);
    center_loss_final<<<1, 1>>>(out);
}